// round 2
// baseline (speedup 1.0000x reference)
#include <cuda_runtime.h>
#include <math.h>

#define NPART 262144
#define FDIM  256
#define BD    8
#define MM    64
#define M3    262144
#define HID   64
#define FULLMASK 0xFFFFFFFFu

/* ------------------------------ scratch (static device memory, no allocs) */
__device__ float4 g_rmesh4[M3 * 2];          /* real mesh  [x][y][z][c]  8 MB */
__device__ float2 g_cmesh[BD * M3];          /* complex    [c][x][y][z] 16 MB */
__device__ float4 g_fmesh4[M3 * 2];          /* filtered   [x][y][z][c]  8 MB */
__device__ float  g_source[NPART * BD];      /* particle charges         8 MB */
__device__ float  g_spec[3073];
__device__ float  g_sums[BD];
__device__ float  g_invcell[9];
__device__ float  g_ku;
__device__ float  g_cs[BD];                  /* softplus(ch_scale)/M^3 */

/* ------------------------------ complex helpers */
__device__ __forceinline__ float2 cmul(float2 a, float2 b) {
    return make_float2(a.x * b.x - a.y * b.y, a.x * b.y + a.y * b.x);
}
__device__ __forceinline__ float2 cadd(float2 a, float2 b) { return make_float2(a.x + b.x, a.y + b.y); }
__device__ __forceinline__ float2 csub(float2 a, float2 b) { return make_float2(a.x - b.x, a.y - b.y); }

/* signed frequency of storage index p (base-8 digit-reversed order) */
__device__ __forceinline__ int sdr(int p) {
    int d = ((p & 7) << 3) | (p >> 3);
    return (d < 32) ? d : d - 64;
}

/* 8-point DFT in registers. INV=0: W8=e^{-2pi i/8}; INV=1: conjugate. */
template <int INV>
__device__ __forceinline__ void dft8(float2 v[8]) {
    float2 e0 = v[0], e1 = v[2], e2 = v[4], e3 = v[6];
    float2 o0 = v[1], o1 = v[3], o2 = v[5], o3 = v[7];

    float2 t0 = cadd(e0, e2), t1 = csub(e0, e2), t2 = cadd(e1, e3), t3 = csub(e1, e3);
    float2 r3 = INV ? make_float2(-t3.y, t3.x) : make_float2(t3.y, -t3.x);
    float2 E0 = cadd(t0, t2), E2 = csub(t0, t2), E1 = cadd(t1, r3), E3 = csub(t1, r3);

    t0 = cadd(o0, o2); t1 = csub(o0, o2); t2 = cadd(o1, o3); t3 = csub(o1, o3);
    r3 = INV ? make_float2(-t3.y, t3.x) : make_float2(t3.y, -t3.x);
    float2 O0 = cadd(t0, t2), O2 = csub(t0, t2), O1 = cadd(t1, r3), O3 = csub(t1, r3);

    const float r = 0.70710678118654752f;
    float2 w1 = INV ? make_float2(r, r)  : make_float2(r, -r);
    float2 w3 = INV ? make_float2(-r, r) : make_float2(-r, -r);
    float2 p0 = O0;
    float2 p1 = cmul(O1, w1);
    float2 p2 = INV ? make_float2(-O2.y, O2.x) : make_float2(O2.y, -O2.x);
    float2 p3 = cmul(O3, w3);

    v[0] = cadd(E0, p0); v[4] = csub(E0, p0);
    v[1] = cadd(E1, p1); v[5] = csub(E1, p1);
    v[2] = cadd(E2, p2); v[6] = csub(E2, p2);
    v[3] = cadd(E3, p3); v[7] = csub(E3, p3);
}

/* 64-pt FFT on strided smem line (split re/im). Forward: natural->dr8.
   Inverse: dr8->natural, unscaled (x64). tw[k]=e^{-2pi i k/64}.         */
template <int INV>
__device__ void fft64(float* __restrict__ sr, float* __restrict__ si, int st,
                      const float* __restrict__ twr, const float* __restrict__ twi) {
    float2 v[8];
    if (!INV) {
        #pragma unroll 1
        for (int n1 = 0; n1 < 8; n1++) {
            #pragma unroll
            for (int m = 0; m < 8; m++) {
                int idx = (n1 + 8 * m) * st;
                v[m] = make_float2(sr[idx], si[idx]);
            }
            dft8<0>(v);
            #pragma unroll
            for (int t = 0; t < 8; t++) {
                int k = (n1 * t) & 63;
                float2 w = make_float2(twr[k], twi[k]);
                float2 r = cmul(v[t], w);
                int idx = (n1 + 8 * t) * st;
                sr[idx] = r.x; si[idx] = r.y;
            }
        }
        #pragma unroll 1
        for (int g = 0; g < 8; g++) {
            #pragma unroll
            for (int m = 0; m < 8; m++) {
                int idx = (8 * g + m) * st;
                v[m] = make_float2(sr[idx], si[idx]);
            }
            dft8<0>(v);
            #pragma unroll
            for (int t = 0; t < 8; t++) {
                int idx = (8 * g + t) * st;
                sr[idx] = v[t].x; si[idx] = v[t].y;
            }
        }
    } else {
        #pragma unroll 1
        for (int g = 0; g < 8; g++) {
            #pragma unroll
            for (int m = 0; m < 8; m++) {
                int idx = (8 * g + m) * st;
                v[m] = make_float2(sr[idx], si[idx]);
            }
            dft8<1>(v);
            #pragma unroll
            for (int t = 0; t < 8; t++) {
                int idx = (8 * g + t) * st;
                sr[idx] = v[t].x; si[idx] = v[t].y;
            }
        }
        #pragma unroll 1
        for (int n1 = 0; n1 < 8; n1++) {
            #pragma unroll
            for (int m = 0; m < 8; m++) {
                int idx = (n1 + 8 * m) * st;
                int k = (n1 * m) & 63;
                float2 w = make_float2(twr[k], -twi[k]);   /* conjugate */
                v[m] = cmul(make_float2(sr[idx], si[idx]), w);
            }
            dft8<1>(v);
            #pragma unroll
            for (int t = 0; t < 8; t++) {
                int idx = (n1 + 8 * t) * st;
                sr[idx] = v[t].x; si[idx] = v[t].y;
            }
        }
    }
}

/* ------------------------------ setup */
__global__ void k_setup(const float* __restrict__ cell, const float* __restrict__ ch_raw) {
    int t = threadIdx.x;
    if (t == 0) {
        float a = cell[0], b = cell[1], c = cell[2];
        float d = cell[3], e = cell[4], f = cell[5];
        float g = cell[6], h = cell[7], i = cell[8];
        float A = (e * i - f * h), B = -(d * i - f * g), C = (d * h - e * g);
        float det = a * A + b * B + c * C;
        float id = 1.0f / det;
        g_invcell[0] = A * id;
        g_invcell[1] = -(b * i - c * h) * id;
        g_invcell[2] =  (b * f - c * e) * id;
        g_invcell[3] = B * id;
        g_invcell[4] =  (a * i - c * g) * id;
        g_invcell[5] = -(a * f - c * d) * id;
        g_invcell[6] = C * id;
        g_invcell[7] = -(a * h - b * g) * id;
        g_invcell[8] =  (a * e - b * d) * id;
        float r0 = g_invcell[0], r1 = g_invcell[1], r2 = g_invcell[2];
        g_ku = 6.283185307179586f * sqrtf(r0 * r0 + r1 * r1 + r2 * r2);
    }
    if (t < BD) {
        g_sums[t] = 0.f;
        float x = ch_raw[t];
        float sp = (x > 20.f) ? x : log1pf(expf(x));
        g_cs[t] = sp * (1.0f / (float)M3);
    }
}

__global__ void k_zero() {
    int i = blockIdx.x * blockDim.x + threadIdx.x;
    g_rmesh4[i] = make_float4(0.f, 0.f, 0.f, 0.f);
}

/* radial MLP table: block = one s value (0..3072), 64 threads */
__global__ void k_radial(const float* __restrict__ w1, const float* __restrict__ b1,
                         const float* __restrict__ w2, const float* __restrict__ b2,
                         const float* __restrict__ w3, const float* __restrict__ b3) {
    int s = blockIdx.x;
    int t = threadIdx.x;
    if (s == 0) { if (t == 0) g_spec[0] = 0.f; return; }
    __shared__ float h1[HID];
    __shared__ float red[HID];

    float k = g_ku * sqrtf((float)s);
    float x0 = log1pf(k);
    float f0 = x0, f1 = x0 * x0, f2 = 1.0f / k;

    float z = w1[t * 3 + 0] * f0 + w1[t * 3 + 1] * f1 + w1[t * 3 + 2] * f2 + b1[t];
    h1[t] = z / (1.0f + expf(-z));
    __syncthreads();

    float acc = b2[t];
    #pragma unroll 8
    for (int j = 0; j < HID; j++) acc += w2[t * HID + j] * h1[j];
    float h2 = acc / (1.0f + expf(-acc));
    red[t] = h2 * w3[t];
    __syncthreads();
    if (t == 0) {
        float tot = b3[0];
        for (int j = 0; j < HID; j++) tot += red[j];
        float learned = (tot > 20.f) ? tot : log1pf(expf(tot));
        g_spec[s] = (12.566370614359172f / (k * k)) * learned;
    }
}

/* LayerNorm + low-rank projection; one warp per particle (grid-stride) */
__global__ void k_lnproj(const float* __restrict__ h, const float* __restrict__ ln_w,
                         const float* __restrict__ ln_b, const float* __restrict__ in_w,
                         const float* __restrict__ in_b) {
    __shared__ float bsum[BD];
    int tid = threadIdx.x;
    if (tid < BD) bsum[tid] = 0.f;
    __syncthreads();

    int lane = tid & 31;
    int warpId = (blockIdx.x * blockDim.x + tid) >> 5;
    int nWarps = (gridDim.x * blockDim.x) >> 5;
    int f0 = lane * 8;

    float lw[8], lb[8], wreg[BD][8];
    #pragma unroll
    for (int j = 0; j < 8; j++) { lw[j] = ln_w[f0 + j]; lb[j] = ln_b[f0 + j]; }
    #pragma unroll
    for (int c = 0; c < BD; c++)
        #pragma unroll
        for (int j = 0; j < 8; j++) wreg[c][j] = in_w[c * FDIM + f0 + j];
    float inb = (lane < BD) ? in_b[lane] : 0.f;

    float accSum = 0.f;
    for (int p = warpId; p < NPART; p += nWarps) {
        const float4* hp = (const float4*)(h + (size_t)p * FDIM + f0);
        float4 A = hp[0], B = hp[1];
        float x[8] = {A.x, A.y, A.z, A.w, B.x, B.y, B.z, B.w};
        float s1 = 0.f, s2 = 0.f;
        #pragma unroll
        for (int j = 0; j < 8; j++) { s1 += x[j]; s2 += x[j] * x[j]; }
        #pragma unroll
        for (int m = 16; m >= 1; m >>= 1) {
            s1 += __shfl_xor_sync(FULLMASK, s1, m);
            s2 += __shfl_xor_sync(FULLMASK, s2, m);
        }
        float mu = s1 * (1.0f / FDIM);
        float var = s2 * (1.0f / FDIM) - mu * mu;
        float rs = rsqrtf(var + 1e-5f);
        float nm[8];
        #pragma unroll
        for (int j = 0; j < 8; j++) nm[j] = (x[j] - mu) * rs * lw[j] + lb[j];

        #pragma unroll
        for (int c = 0; c < BD; c++) {
            float pc = 0.f;
            #pragma unroll
            for (int j = 0; j < 8; j++) pc += nm[j] * wreg[c][j];
            #pragma unroll
            for (int m = 16; m >= 1; m >>= 1) pc += __shfl_xor_sync(FULLMASK, pc, m);
            if (lane == c) {
                float val = pc + inb;
                g_source[(size_t)p * BD + c] = val;
                accSum += val;
            }
        }
    }
    if (lane < BD) atomicAdd(&bsum[lane], accSum);
    __syncthreads();
    if (tid < BD) atomicAdd(&g_sums[tid], bsum[tid]);
}

/* P2M scatter: one thread per particle, vector red.global */
__global__ void k_scatter(const float* __restrict__ pos) {
    int p = blockIdx.x * blockDim.x + threadIdx.x;
    if (p >= NPART) return;

    float mean[BD];
    #pragma unroll
    for (int c = 0; c < BD; c++) mean[c] = g_sums[c] * (1.0f / (float)NPART);

    float px = pos[p * 3 + 0], py = pos[p * 3 + 1], pz = pos[p * 3 + 2];
    float fr[3];
    #pragma unroll
    for (int j = 0; j < 3; j++) {
        float f = px * g_invcell[0 * 3 + j] + py * g_invcell[1 * 3 + j] + pz * g_invcell[2 * 3 + j];
        f -= floorf(f);
        fr[j] = f * (float)MM;
    }
    int   bi[3]; float fo[3];
    #pragma unroll
    for (int j = 0; j < 3; j++) { float b = floorf(fr[j]); bi[j] = (int)b; fo[j] = fr[j] - b; }

    float s[BD];
    const float4* sp = (const float4*)(g_source + (size_t)p * BD);
    float4 SA = sp[0], SB = sp[1];
    s[0] = SA.x - mean[0]; s[1] = SA.y - mean[1]; s[2] = SA.z - mean[2]; s[3] = SA.w - mean[3];
    s[4] = SB.x - mean[4]; s[5] = SB.y - mean[5]; s[6] = SB.z - mean[6]; s[7] = SB.w - mean[7];

    float* mesh = (float*)g_rmesh4;
    #pragma unroll
    for (int cn = 0; cn < 8; cn++) {
        int ox = (cn >> 2) & 1, oy = (cn >> 1) & 1, oz = cn & 1;
        float w = (ox ? fo[0] : 1.f - fo[0]) * (oy ? fo[1] : 1.f - fo[1]) * (oz ? fo[2] : 1.f - fo[2]);
        int ix = (bi[0] + ox) & 63, iy = (bi[1] + oy) & 63, iz = (bi[2] + oz) & 63;
        float* dst = mesh + (size_t)(((ix * MM + iy) * MM + iz)) * BD;
        asm volatile("red.global.add.v4.f32 [%0], {%1, %2, %3, %4};"
                     :: "l"(dst), "f"(s[0] * w), "f"(s[1] * w), "f"(s[2] * w), "f"(s[3] * w) : "memory");
        asm volatile("red.global.add.v4.f32 [%0], {%1, %2, %3, %4};"
                     :: "l"(dst + 4), "f"(s[4] * w), "f"(s[5] * w), "f"(s[6] * w), "f"(s[7] * w) : "memory");
    }
}

#define PITCH 65

/* stage A: forward FFT along z then y. block=(c,x), 64 threads */
__global__ void k_fft_zy() {
    __shared__ float sr[MM * PITCH], si[MM * PITCH], twr[MM], twi[MM];
    int b = blockIdx.x;
    int c = b >> 6, x = b & 63;
    int t = threadIdx.x;
    {
        float sv, cv; sincospif(-(float)t / 32.0f, &sv, &cv);
        twr[t] = cv; twi[t] = sv;
    }
    const float* mesh = (const float*)g_rmesh4;
    for (int y = 0; y < MM; y++) {
        sr[y * PITCH + t] = mesh[(size_t)(((x * MM + y) * MM + t)) * BD + c];
        si[y * PITCH + t] = 0.f;
    }
    __syncthreads();
    fft64<0>(&sr[t * PITCH], &si[t * PITCH], 1, twr, twi);     /* along z, line y=t */
    __syncthreads();
    fft64<0>(&sr[t], &si[t], PITCH, twr, twi);                 /* along y, col z=t */
    __syncthreads();
    float2* out = g_cmesh + (size_t)(c * MM + x) * MM * MM;
    for (int y = 0; y < MM; y++)
        out[y * MM + t] = make_float2(sr[y * PITCH + t], si[y * PITCH + t]);
}

/* stage C: forward FFT along x, spectral filter, inverse FFT along x. block=(c,y) */
__global__ void k_fft_x_filter() {
    __shared__ float sr[MM * PITCH], si[MM * PITCH], twr[MM], twi[MM];
    int b = blockIdx.x;
    int c = b >> 6, y = b & 63;
    int t = threadIdx.x;
    {
        float sv, cv; sincospif(-(float)t / 32.0f, &sv, &cv);
        twr[t] = cv; twi[t] = sv;
    }
    float2* base = g_cmesh + (size_t)c * M3;
    for (int x = 0; x < MM; x++) {
        float2 v = base[(size_t)(x * MM + y) * MM + t];
        sr[x * PITCH + t] = v.x; si[x * PITCH + t] = v.y;
    }
    __syncthreads();
    fft64<0>(&sr[t], &si[t], PITCH, twr, twi);                 /* along x, col z=t */

    int ky = sdr(y), kz = sdr(t);
    int syz = ky * ky + kz * kz;
    float csc = g_cs[c];
    #pragma unroll 4
    for (int px = 0; px < MM; px++) {
        int kx = sdr(px);
        float m = g_spec[kx * kx + syz] * csc;
        sr[px * PITCH + t] *= m;
        si[px * PITCH + t] *= m;
    }
    fft64<1>(&sr[t], &si[t], PITCH, twr, twi);                 /* inverse along x */
    __syncthreads();
    for (int x = 0; x < MM; x++)
        base[(size_t)(x * MM + y) * MM + t] = make_float2(sr[x * PITCH + t], si[x * PITCH + t]);
}

/* stage D: inverse FFT along y then z, write real mesh. block=(c,x) */
__global__ void k_ifft_yz() {
    __shared__ float sr[MM * PITCH], si[MM * PITCH], twr[MM], twi[MM];
    int b = blockIdx.x;
    int c = b >> 6, x = b & 63;
    int t = threadIdx.x;
    {
        float sv, cv; sincospif(-(float)t / 32.0f, &sv, &cv);
        twr[t] = cv; twi[t] = sv;
    }
    const float2* in = g_cmesh + (size_t)(c * MM + x) * MM * MM;
    for (int y = 0; y < MM; y++) {
        float2 v = in[y * MM + t];
        sr[y * PITCH + t] = v.x; si[y * PITCH + t] = v.y;
    }
    __syncthreads();
    fft64<1>(&sr[t], &si[t], PITCH, twr, twi);                 /* inverse along y */
    __syncthreads();
    fft64<1>(&sr[t * PITCH], &si[t * PITCH], 1, twr, twi);     /* inverse along z */
    __syncthreads();
    float* out = (float*)g_fmesh4;
    for (int y = 0; y < MM; y++)
        out[(size_t)(((x * MM + y) * MM + t)) * BD + c] = sr[y * PITCH + t];
}

/* M2P gather + output projection + residual; one warp per particle */
__global__ void k_gather(const float* __restrict__ h, const float* __restrict__ pos,
                         const float* __restrict__ out_w, const float* __restrict__ gatep,
                         float* __restrict__ out) {
    int tid = threadIdx.x;
    int lane = tid & 31;
    int warpId = (blockIdx.x * blockDim.x + tid) >> 5;
    int nWarps = (gridDim.x * blockDim.x) >> 5;
    int f0 = lane * 8;

    float ow[8][BD];
    #pragma unroll
    for (int j = 0; j < 8; j++)
        #pragma unroll
        for (int c = 0; c < BD; c++) ow[j][c] = out_w[(f0 + j) * BD + c];
    float gate = gatep[0];
    float ic[9];
    #pragma unroll
    for (int j = 0; j < 9; j++) ic[j] = g_invcell[j];
    const float* mesh = (const float*)g_fmesh4;

    for (int p = warpId; p < NPART; p += nWarps) {
        float px = pos[p * 3 + 0], py = pos[p * 3 + 1], pz = pos[p * 3 + 2];
        float fr[3];
        #pragma unroll
        for (int j = 0; j < 3; j++) {
            float f = px * ic[0 * 3 + j] + py * ic[1 * 3 + j] + pz * ic[2 * 3 + j];
            f -= floorf(f);
            fr[j] = f * (float)MM;
        }
        int bi[3]; float fo[3];
        #pragma unroll
        for (int j = 0; j < 3; j++) { float bb = floorf(fr[j]); bi[j] = (int)bb; fo[j] = fr[j] - bb; }

        int cn = lane & 7;
        int ox = (cn >> 2) & 1, oy = (cn >> 1) & 1, oz = cn & 1;
        float w = (ox ? fo[0] : 1.f - fo[0]) * (oy ? fo[1] : 1.f - fo[1]) * (oz ? fo[2] : 1.f - fo[2]);
        int ix = (bi[0] + ox) & 63, iy = (bi[1] + oy) & 63, iz = (bi[2] + oz) & 63;
        const float4* src = (const float4*)(mesh + (size_t)(((ix * MM + iy) * MM + iz)) * BD);
        float4 GA = src[0], GB = src[1];
        float g[8] = {GA.x * w, GA.y * w, GA.z * w, GA.w * w, GB.x * w, GB.y * w, GB.z * w, GB.w * w};
        #pragma unroll
        for (int m = 1; m < 8; m <<= 1)
            #pragma unroll
            for (int j = 0; j < 8; j++) g[j] += __shfl_xor_sync(FULLMASK, g[j], m);

        const float4* hp = (const float4*)(h + (size_t)p * FDIM + f0);
        float4 A = hp[0], B = hp[1];
        float hv[8] = {A.x, A.y, A.z, A.w, B.x, B.y, B.z, B.w};
        float ov[8];
        #pragma unroll
        for (int j = 0; j < 8; j++) {
            float acc = 0.f;
            #pragma unroll
            for (int c = 0; c < BD; c++) acc += g[c] * ow[j][c];
            ov[j] = hv[j] + gate * acc;
        }
        float4* op = (float4*)(out + (size_t)p * FDIM + f0);
        op[0] = make_float4(ov[0], ov[1], ov[2], ov[3]);
        op[1] = make_float4(ov[4], ov[5], ov[6], ov[7]);
    }
}

extern "C" void kernel_launch(void* const* d_in, const int* in_sizes, int n_in,
                              void* d_out, int out_size) {
    const float* h       = (const float*)d_in[0];
    const float* pos     = (const float*)d_in[1];
    const float* cell    = (const float*)d_in[2];
    const float* ln_w    = (const float*)d_in[3];
    const float* ln_b    = (const float*)d_in[4];
    const float* in_w    = (const float*)d_in[5];
    const float* in_b    = (const float*)d_in[6];
    const float* out_w   = (const float*)d_in[7];
    const float* f_w1    = (const float*)d_in[8];
    const float* f_b1    = (const float*)d_in[9];
    const float* f_w2    = (const float*)d_in[10];
    const float* f_b2    = (const float*)d_in[11];
    const float* f_w3    = (const float*)d_in[12];
    const float* f_b3    = (const float*)d_in[13];
    const float* ch_raw  = (const float*)d_in[14];
    const float* gate    = (const float*)d_in[15];
    float* out = (float*)d_out;

    k_setup<<<1, 32>>>(cell, ch_raw);
    k_zero<<<2048, 256>>>();
    k_radial<<<3073, 64>>>(f_w1, f_b1, f_w2, f_b2, f_w3, f_b3);
    k_lnproj<<<1024, 256>>>(h, ln_w, ln_b, in_w, in_b);
    k_scatter<<<1024, 256>>>(pos);
    k_fft_zy<<<512, 64>>>();
    k_fft_x_filter<<<512, 64>>>();
    k_ifft_yz<<<512, 64>>>();
    k_gather<<<1024, 256>>>(h, pos, out_w, gate, out);
}

// round 4
// speedup vs baseline: 1.2399x; 1.2399x over previous
#include <cuda_runtime.h>
#include <math.h>

#define NPART 262144
#define FDIM  256
#define BD    8
#define MM    64
#define M3    262144
#define HID   64
#define FULLMASK 0xFFFFFFFFu

/* ------------------------------ scratch (static device memory, no allocs) */
__device__ float4 g_rmesh4[M3 * 2];          /* real mesh  [x][y][z][c]  8 MB */
__device__ float2 g_cmesh[BD * M3];          /* complex    [c][x][y][z] 16 MB */
__device__ float4 g_fmesh4[M3 * 2];          /* filtered   [x][y][z][c]  8 MB */
__device__ float  g_source[NPART * BD];      /* particle charges         8 MB */
__device__ float  g_spec[3073];
__device__ float  g_sums[BD];
__device__ float  g_invcell[9];
__device__ float  g_ku;
__device__ float  g_cs[BD];                  /* softplus(ch_scale)/M^3 */

/* ------------------------------ complex helpers */
__device__ __forceinline__ float2 cmul(float2 a, float2 b) {
    return make_float2(a.x * b.x - a.y * b.y, a.x * b.y + a.y * b.x);
}
__device__ __forceinline__ float2 cadd(float2 a, float2 b) { return make_float2(a.x + b.x, a.y + b.y); }
__device__ __forceinline__ float2 csub(float2 a, float2 b) { return make_float2(a.x - b.x, a.y - b.y); }

/* signed frequency of storage index p (base-8 digit-reversed order) */
__device__ __forceinline__ int sdr(int p) {
    int d = ((p & 7) << 3) | (p >> 3);
    return (d < 32) ? d : d - 64;
}

/* Reduce-scatter a[8] over channel bits with masks 1,2,4.
   Returns: per-lane value = sum over the lane's 8-lane group (lanes differing
   in bits 0..2) of channel (lane&7). 7 shuffles. */
__device__ __forceinline__ float rscatter8(const float v[8], int lane) {
    float u[4];
    bool b0 = (lane & 1);
    #pragma unroll
    for (int j = 0; j < 4; j++) {
        float a = v[2 * j], b = v[2 * j + 1];
        float keep = b0 ? b : a;
        float send = b0 ? a : b;
        u[j] = keep + __shfl_xor_sync(FULLMASK, send, 1);
    }
    bool b1 = (lane & 2);
    float w[2];
    #pragma unroll
    for (int j = 0; j < 2; j++) {
        float a = u[2 * j], b = u[2 * j + 1];
        float keep = b1 ? b : a;
        float send = b1 ? a : b;
        w[j] = keep + __shfl_xor_sync(FULLMASK, send, 2);
    }
    bool b2 = (lane & 4);
    float keep = b2 ? w[1] : w[0];
    float send = b2 ? w[0] : w[1];
    return keep + __shfl_xor_sync(FULLMASK, send, 4);
}

/* full 32-lane version: every lane ends with total of channel (lane&7). 9 shuffles */
__device__ __forceinline__ float rscatter8_full(const float v[8], int lane) {
    float t = rscatter8(v, lane);
    t += __shfl_xor_sync(FULLMASK, t, 8);
    t += __shfl_xor_sync(FULLMASK, t, 16);
    return t;
}

/* 8-point DFT in registers. INV=0: W8=e^{-2pi i/8}; INV=1: conjugate. */
template <int INV>
__device__ __forceinline__ void dft8(float2 v[8]) {
    float2 e0 = v[0], e1 = v[2], e2 = v[4], e3 = v[6];
    float2 o0 = v[1], o1 = v[3], o2 = v[5], o3 = v[7];

    float2 t0 = cadd(e0, e2), t1 = csub(e0, e2), t2 = cadd(e1, e3), t3 = csub(e1, e3);
    float2 r3 = INV ? make_float2(-t3.y, t3.x) : make_float2(t3.y, -t3.x);
    float2 E0 = cadd(t0, t2), E2 = csub(t0, t2), E1 = cadd(t1, r3), E3 = csub(t1, r3);

    t0 = cadd(o0, o2); t1 = csub(o0, o2); t2 = cadd(o1, o3); t3 = csub(o1, o3);
    r3 = INV ? make_float2(-t3.y, t3.x) : make_float2(t3.y, -t3.x);
    float2 O0 = cadd(t0, t2), O2 = csub(t0, t2), O1 = cadd(t1, r3), O3 = csub(t1, r3);

    const float r = 0.70710678118654752f;
    float2 w1 = INV ? make_float2(r, r)  : make_float2(r, -r);
    float2 w3 = INV ? make_float2(-r, r) : make_float2(-r, -r);
    float2 p0 = O0;
    float2 p1 = cmul(O1, w1);
    float2 p2 = INV ? make_float2(-O2.y, O2.x) : make_float2(O2.y, -O2.x);
    float2 p3 = cmul(O3, w3);

    v[0] = cadd(E0, p0); v[4] = csub(E0, p0);
    v[1] = cadd(E1, p1); v[5] = csub(E1, p1);
    v[2] = cadd(E2, p2); v[6] = csub(E2, p2);
    v[3] = cadd(E3, p3); v[7] = csub(E3, p3);
}

/* 64-pt FFT on strided smem line (split re/im). Forward: natural->dr8.
   Inverse: dr8->natural, unscaled (x64). tw[k]=e^{-2pi i k/64}.         */
template <int INV>
__device__ void fft64(float* __restrict__ sr, float* __restrict__ si, int st,
                      const float* __restrict__ twr, const float* __restrict__ twi) {
    float2 v[8];
    if (!INV) {
        #pragma unroll 1
        for (int n1 = 0; n1 < 8; n1++) {
            #pragma unroll
            for (int m = 0; m < 8; m++) {
                int idx = (n1 + 8 * m) * st;
                v[m] = make_float2(sr[idx], si[idx]);
            }
            dft8<0>(v);
            #pragma unroll
            for (int t = 0; t < 8; t++) {
                int k = (n1 * t) & 63;
                float2 w = make_float2(twr[k], twi[k]);
                float2 r = cmul(v[t], w);
                int idx = (n1 + 8 * t) * st;
                sr[idx] = r.x; si[idx] = r.y;
            }
        }
        #pragma unroll 1
        for (int g = 0; g < 8; g++) {
            #pragma unroll
            for (int m = 0; m < 8; m++) {
                int idx = (8 * g + m) * st;
                v[m] = make_float2(sr[idx], si[idx]);
            }
            dft8<0>(v);
            #pragma unroll
            for (int t = 0; t < 8; t++) {
                int idx = (8 * g + t) * st;
                sr[idx] = v[t].x; si[idx] = v[t].y;
            }
        }
    } else {
        #pragma unroll 1
        for (int g = 0; g < 8; g++) {
            #pragma unroll
            for (int m = 0; m < 8; m++) {
                int idx = (8 * g + m) * st;
                v[m] = make_float2(sr[idx], si[idx]);
            }
            dft8<1>(v);
            #pragma unroll
            for (int t = 0; t < 8; t++) {
                int idx = (8 * g + t) * st;
                sr[idx] = v[t].x; si[idx] = v[t].y;
            }
        }
        #pragma unroll 1
        for (int n1 = 0; n1 < 8; n1++) {
            #pragma unroll
            for (int m = 0; m < 8; m++) {
                int idx = (n1 + 8 * m) * st;
                int k = (n1 * m) & 63;
                float2 w = make_float2(twr[k], -twi[k]);   /* conjugate */
                v[m] = cmul(make_float2(sr[idx], si[idx]), w);
            }
            dft8<1>(v);
            #pragma unroll
            for (int t = 0; t < 8; t++) {
                int idx = (n1 + 8 * t) * st;
                sr[idx] = v[t].x; si[idx] = v[t].y;
            }
        }
    }
}

/* ------------------------------ setup */
__global__ void k_setup(const float* __restrict__ cell, const float* __restrict__ ch_raw) {
    int t = threadIdx.x;
    if (t == 0) {
        float a = cell[0], b = cell[1], c = cell[2];
        float d = cell[3], e = cell[4], f = cell[5];
        float g = cell[6], h = cell[7], i = cell[8];
        float A = (e * i - f * h), B = -(d * i - f * g), C = (d * h - e * g);
        float det = a * A + b * B + c * C;
        float id = 1.0f / det;
        g_invcell[0] = A * id;
        g_invcell[1] = -(b * i - c * h) * id;
        g_invcell[2] =  (b * f - c * e) * id;
        g_invcell[3] = B * id;
        g_invcell[4] =  (a * i - c * g) * id;
        g_invcell[5] = -(a * f - c * d) * id;
        g_invcell[6] = C * id;
        g_invcell[7] = -(a * h - b * g) * id;
        g_invcell[8] =  (a * e - b * d) * id;
        float r0 = g_invcell[0], r1 = g_invcell[1], r2 = g_invcell[2];
        g_ku = 6.283185307179586f * sqrtf(r0 * r0 + r1 * r1 + r2 * r2);
    }
    if (t < BD) {
        g_sums[t] = 0.f;
        float x = ch_raw[t];
        float sp = (x > 20.f) ? x : log1pf(expf(x));
        g_cs[t] = sp * (1.0f / (float)M3);
    }
}

__global__ void k_zero() {
    int i = blockIdx.x * blockDim.x + threadIdx.x;
    g_rmesh4[i] = make_float4(0.f, 0.f, 0.f, 0.f);
}

/* radial MLP table: block = one s value (0..3072), 64 threads */
__global__ void k_radial(const float* __restrict__ w1, const float* __restrict__ b1,
                         const float* __restrict__ w2, const float* __restrict__ b2,
                         const float* __restrict__ w3, const float* __restrict__ b3) {
    int s = blockIdx.x;
    int t = threadIdx.x;
    if (s == 0) { if (t == 0) g_spec[0] = 0.f; return; }
    __shared__ float h1[HID];
    __shared__ float red[HID];

    float k = g_ku * sqrtf((float)s);
    float x0 = log1pf(k);
    float f0 = x0, f1 = x0 * x0, f2 = 1.0f / k;

    float z = w1[t * 3 + 0] * f0 + w1[t * 3 + 1] * f1 + w1[t * 3 + 2] * f2 + b1[t];
    h1[t] = z / (1.0f + expf(-z));
    __syncthreads();

    float acc = b2[t];
    #pragma unroll 8
    for (int j = 0; j < HID; j++) acc += w2[t * HID + j] * h1[j];
    float h2 = acc / (1.0f + expf(-acc));
    red[t] = h2 * w3[t];
    __syncthreads();
    if (t == 0) {
        float tot = b3[0];
        for (int j = 0; j < HID; j++) tot += red[j];
        float learned = (tot > 20.f) ? tot : log1pf(expf(tot));
        g_spec[s] = (12.566370614359172f / (k * k)) * learned;
    }
}

/* LayerNorm + low-rank projection; one warp per particle (grid-stride),
   LN affine folded into weights, reduce-scatter reductions, prefetch. */
__global__ void __launch_bounds__(256, 2)
k_lnproj(const float* __restrict__ h, const float* __restrict__ ln_w,
         const float* __restrict__ ln_b, const float* __restrict__ in_w,
         const float* __restrict__ in_b) {
    __shared__ float bsum[BD];
    int tid = threadIdx.x;
    if (tid < BD) bsum[tid] = 0.f;
    __syncthreads();

    int lane = tid & 31;
    int warpId = (blockIdx.x * blockDim.x + tid) >> 5;
    int nWarps = (gridDim.x * blockDim.x) >> 5;
    int f0 = lane * 8;

    /* fold ln affine: wl[c][j] = ln_w[f]*in_w[c][f]; ws[c]=sum_j wl */
    float wl[BD][8], ws[BD];
    float bc[BD];                                  /* ln_b contribution */
    #pragma unroll
    for (int c = 0; c < BD; c++) {
        float s = 0.f, sb = 0.f;
        #pragma unroll
        for (int j = 0; j < 8; j++) {
            float w = in_w[c * FDIM + f0 + j];
            float v = ln_w[f0 + j] * w;
            wl[c][j] = v;
            s += v;
            sb += ln_b[f0 + j] * w;
        }
        ws[c] = s; bc[c] = sb;
    }
    /* per-channel constant bias: in_b[c] + sum_f ln_b*in_w */
    float cbias = rscatter8_full(bc, lane) + in_b[lane & 7];

    float accSum = 0.f;
    int p = warpId;
    const float4* hp = (const float4*)(h + (size_t)p * FDIM + f0);
    float4 A = hp[0], B = hp[1];
    for (; p < NPART; ) {
        int pn = p + nWarps;
        float4 An, Bn;
        if (pn < NPART) {
            const float4* hn = (const float4*)(h + (size_t)pn * FDIM + f0);
            An = hn[0]; Bn = hn[1];
        }
        float x[8] = {A.x, A.y, A.z, A.w, B.x, B.y, B.z, B.w};
        float s1 = 0.f, s2 = 0.f;
        #pragma unroll
        for (int j = 0; j < 8; j++) { s1 += x[j]; s2 += x[j] * x[j]; }
        /* packed (s1,s2) reduce-scatter over mask16, butterflies, broadcast */
        {
            bool b4 = (lane & 16);
            float keep = b4 ? s2 : s1;
            float send = b4 ? s1 : s2;
            keep += __shfl_xor_sync(FULLMASK, send, 16);
            keep += __shfl_xor_sync(FULLMASK, keep, 1);
            keep += __shfl_xor_sync(FULLMASK, keep, 2);
            keep += __shfl_xor_sync(FULLMASK, keep, 4);
            keep += __shfl_xor_sync(FULLMASK, keep, 8);
            s1 = __shfl_sync(FULLMASK, keep, lane & 15);
            s2 = __shfl_sync(FULLMASK, keep, (lane & 15) | 16);
        }
        float mu = s1 * (1.0f / FDIM);
        float var = s2 * (1.0f / FDIM) - mu * mu;
        float rs = rsqrtf(var + 1e-5f);

        float v[BD];
        #pragma unroll
        for (int c = 0; c < BD; c++) {
            float d = 0.f;
            #pragma unroll
            for (int j = 0; j < 8; j++) d += x[j] * wl[c][j];
            v[c] = d - mu * ws[c];
        }
        float t = rscatter8_full(v, lane) * rs + cbias;   /* channel lane&7 */
        if (lane < BD) {
            g_source[(size_t)p * BD + lane] = t;
            accSum += t;
        }
        A = An; B = Bn; p = pn;
    }
    if (lane < BD) atomicAdd(&bsum[lane], accSum);
    __syncthreads();
    if (tid < BD) atomicAdd(&g_sums[tid], bsum[tid]);
}

/* P2M scatter: one thread per particle, vector red.global */
__global__ void k_scatter(const float* __restrict__ pos) {
    int p = blockIdx.x * blockDim.x + threadIdx.x;
    if (p >= NPART) return;

    float mean[BD];
    #pragma unroll
    for (int c = 0; c < BD; c++) mean[c] = g_sums[c] * (1.0f / (float)NPART);

    float px = pos[p * 3 + 0], py = pos[p * 3 + 1], pz = pos[p * 3 + 2];
    float fr[3];
    #pragma unroll
    for (int j = 0; j < 3; j++) {
        float f = px * g_invcell[0 * 3 + j] + py * g_invcell[1 * 3 + j] + pz * g_invcell[2 * 3 + j];
        f -= floorf(f);
        fr[j] = f * (float)MM;
    }
    int   bi[3]; float fo[3];
    #pragma unroll
    for (int j = 0; j < 3; j++) { float b = floorf(fr[j]); bi[j] = (int)b; fo[j] = fr[j] - b; }

    float s[BD];
    const float4* sp = (const float4*)(g_source + (size_t)p * BD);
    float4 SA = sp[0], SB = sp[1];
    s[0] = SA.x - mean[0]; s[1] = SA.y - mean[1]; s[2] = SA.z - mean[2]; s[3] = SA.w - mean[3];
    s[4] = SB.x - mean[4]; s[5] = SB.y - mean[5]; s[6] = SB.z - mean[6]; s[7] = SB.w - mean[7];

    float* mesh = (float*)g_rmesh4;
    #pragma unroll
    for (int cn = 0; cn < 8; cn++) {
        int ox = (cn >> 2) & 1, oy = (cn >> 1) & 1, oz = cn & 1;
        float w = (ox ? fo[0] : 1.f - fo[0]) * (oy ? fo[1] : 1.f - fo[1]) * (oz ? fo[2] : 1.f - fo[2]);
        int ix = (bi[0] + ox) & 63, iy = (bi[1] + oy) & 63, iz = (bi[2] + oz) & 63;
        float* dst = mesh + (size_t)(((ix * MM + iy) * MM + iz)) * BD;
        asm volatile("red.global.add.v4.f32 [%0], {%1, %2, %3, %4};"
                     :: "l"(dst), "f"(s[0] * w), "f"(s[1] * w), "f"(s[2] * w), "f"(s[3] * w) : "memory");
        asm volatile("red.global.add.v4.f32 [%0], {%1, %2, %3, %4};"
                     :: "l"(dst + 4), "f"(s[4] * w), "f"(s[5] * w), "f"(s[6] * w), "f"(s[7] * w) : "memory");
    }
}

#define PITCH 65

/* stage A: forward FFT along z then y. block=(c,x), 64 threads */
__global__ void k_fft_zy() {
    __shared__ float sr[MM * PITCH], si[MM * PITCH], twr[MM], twi[MM];
    int b = blockIdx.x;
    int c = b >> 6, x = b & 63;
    int t = threadIdx.x;
    {
        float sv, cv; sincospif(-(float)t / 32.0f, &sv, &cv);
        twr[t] = cv; twi[t] = sv;
    }
    const float* mesh = (const float*)g_rmesh4;
    for (int y = 0; y < MM; y++) {
        sr[y * PITCH + t] = mesh[(size_t)(((x * MM + y) * MM + t)) * BD + c];
        si[y * PITCH + t] = 0.f;
    }
    __syncthreads();
    fft64<0>(&sr[t * PITCH], &si[t * PITCH], 1, twr, twi);     /* along z, line y=t */
    __syncthreads();
    fft64<0>(&sr[t], &si[t], PITCH, twr, twi);                 /* along y, col z=t */
    __syncthreads();
    float2* out = g_cmesh + (size_t)(c * MM + x) * MM * MM;
    for (int y = 0; y < MM; y++)
        out[y * MM + t] = make_float2(sr[y * PITCH + t], si[y * PITCH + t]);
}

/* stage C: forward FFT along x, spectral filter, inverse FFT along x. block=(c,y) */
__global__ void k_fft_x_filter() {
    __shared__ float sr[MM * PITCH], si[MM * PITCH], twr[MM], twi[MM];
    int b = blockIdx.x;
    int c = b >> 6, y = b & 63;
    int t = threadIdx.x;
    {
        float sv, cv; sincospif(-(float)t / 32.0f, &sv, &cv);
        twr[t] = cv; twi[t] = sv;
    }
    float2* base = g_cmesh + (size_t)c * M3;
    for (int x = 0; x < MM; x++) {
        float2 v = base[(size_t)(x * MM + y) * MM + t];
        sr[x * PITCH + t] = v.x; si[x * PITCH + t] = v.y;
    }
    __syncthreads();
    fft64<0>(&sr[t], &si[t], PITCH, twr, twi);                 /* along x, col z=t */

    int ky = sdr(y), kz = sdr(t);
    int syz = ky * ky + kz * kz;
    float csc = g_cs[c];
    #pragma unroll 4
    for (int px = 0; px < MM; px++) {
        int kx = sdr(px);
        float m = g_spec[kx * kx + syz] * csc;
        sr[px * PITCH + t] *= m;
        si[px * PITCH + t] *= m;
    }
    fft64<1>(&sr[t], &si[t], PITCH, twr, twi);                 /* inverse along x */
    __syncthreads();
    for (int x = 0; x < MM; x++)
        base[(size_t)(x * MM + y) * MM + t] = make_float2(sr[x * PITCH + t], si[x * PITCH + t]);
}

/* stage D: inverse FFT along y then z, write real mesh. block=(c,x) */
__global__ void k_ifft_yz() {
    __shared__ float sr[MM * PITCH], si[MM * PITCH], twr[MM], twi[MM];
    int b = blockIdx.x;
    int c = b >> 6, x = b & 63;
    int t = threadIdx.x;
    {
        float sv, cv; sincospif(-(float)t / 32.0f, &sv, &cv);
        twr[t] = cv; twi[t] = sv;
    }
    const float2* in = g_cmesh + (size_t)(c * MM + x) * MM * MM;
    for (int y = 0; y < MM; y++) {
        float2 v = in[y * MM + t];
        sr[y * PITCH + t] = v.x; si[y * PITCH + t] = v.y;
    }
    __syncthreads();
    fft64<1>(&sr[t], &si[t], PITCH, twr, twi);                 /* inverse along y */
    __syncthreads();
    fft64<1>(&sr[t * PITCH], &si[t * PITCH], 1, twr, twi);     /* inverse along z */
    __syncthreads();
    float* out = (float*)g_fmesh4;
    for (int y = 0; y < MM; y++)
        out[(size_t)(((x * MM + y) * MM + t)) * BD + c] = sr[y * PITCH + t];
}

/* M2P gather + output projection + residual; one warp per particle */
__global__ void __launch_bounds__(256, 2)
k_gather(const float* __restrict__ h, const float* __restrict__ pos,
         const float* __restrict__ out_w, const float* __restrict__ gatep,
         float* __restrict__ out) {
    int tid = threadIdx.x;
    int lane = tid & 31;
    int warpId = (blockIdx.x * blockDim.x + tid) >> 5;
    int nWarps = (gridDim.x * blockDim.x) >> 5;
    int f0 = lane * 8;

    float ow[8][BD];
    #pragma unroll
    for (int j = 0; j < 8; j++)
        #pragma unroll
        for (int c = 0; c < BD; c++) ow[j][c] = out_w[(f0 + j) * BD + c];
    float gate = gatep[0];
    float ic[9];
    #pragma unroll
    for (int j = 0; j < 9; j++) ic[j] = g_invcell[j];
    const float* mesh = (const float*)g_fmesh4;

    int p = warpId;
    const float4* hp0 = (const float4*)(h + (size_t)p * FDIM + f0);
    float4 A = hp0[0], B = hp0[1];
    float px = pos[p * 3 + 0], py = pos[p * 3 + 1], pz = pos[p * 3 + 2];

    for (; p < NPART; ) {
        int pn = p + nWarps;
        float4 An, Bn; float pxn, pyn, pzn;
        if (pn < NPART) {
            const float4* hn = (const float4*)(h + (size_t)pn * FDIM + f0);
            An = hn[0]; Bn = hn[1];
            pxn = pos[pn * 3 + 0]; pyn = pos[pn * 3 + 1]; pzn = pos[pn * 3 + 2];
        }
        float fr[3];
        #pragma unroll
        for (int j = 0; j < 3; j++) {
            float f = px * ic[0 * 3 + j] + py * ic[1 * 3 + j] + pz * ic[2 * 3 + j];
            f -= floorf(f);
            fr[j] = f * (float)MM;
        }
        int bi[3]; float fo[3];
        #pragma unroll
        for (int j = 0; j < 3; j++) { float bb = floorf(fr[j]); bi[j] = (int)bb; fo[j] = fr[j] - bb; }

        int cn = lane & 7;
        int ox = (cn >> 2) & 1, oy = (cn >> 1) & 1, oz = cn & 1;
        float w = (ox ? fo[0] : 1.f - fo[0]) * (oy ? fo[1] : 1.f - fo[1]) * (oz ? fo[2] : 1.f - fo[2]);
        int ix = (bi[0] + ox) & 63, iy = (bi[1] + oy) & 63, iz = (bi[2] + oz) & 63;
        const float4* src = (const float4*)(mesh + (size_t)(((ix * MM + iy) * MM + iz)) * BD);
        float4 GA = src[0], GB = src[1];
        float v[8] = {GA.x * w, GA.y * w, GA.z * w, GA.w * w, GB.x * w, GB.y * w, GB.z * w, GB.w * w};
        /* reduce over the 8 corners (lanes of this 8-lane group), then broadcast */
        float t = rscatter8(v, lane);            /* channel lane&7, group total */
        float g[BD];
        #pragma unroll
        for (int c = 0; c < BD; c++)
            g[c] = __shfl_sync(FULLMASK, t, (lane & 24) | c);

        float hv[8] = {A.x, A.y, A.z, A.w, B.x, B.y, B.z, B.w};
        float ov[8];
        #pragma unroll
        for (int j = 0; j < 8; j++) {
            float acc = 0.f;
            #pragma unroll
            for (int c = 0; c < BD; c++) acc += g[c] * ow[j][c];
            ov[j] = hv[j] + gate * acc;
        }
        float4* op = (float4*)(out + (size_t)p * FDIM + f0);
        op[0] = make_float4(ov[0], ov[1], ov[2], ov[3]);
        op[1] = make_float4(ov[4], ov[5], ov[6], ov[7]);

        A = An; B = Bn; px = pxn; py = pyn; pz = pzn; p = pn;
    }
}

extern "C" void kernel_launch(void* const* d_in, const int* in_sizes, int n_in,
                              void* d_out, int out_size) {
    const float* h       = (const float*)d_in[0];
    const float* pos     = (const float*)d_in[1];
    const float* cell    = (const float*)d_in[2];
    const float* ln_w    = (const float*)d_in[3];
    const float* ln_b    = (const float*)d_in[4];
    const float* in_w    = (const float*)d_in[5];
    const float* in_b    = (const float*)d_in[6];
    const float* out_w   = (const float*)d_in[7];
    const float* f_w1    = (const float*)d_in[8];
    const float* f_b1    = (const float*)d_in[9];
    const float* f_w2    = (const float*)d_in[10];
    const float* f_b2    = (const float*)d_in[11];
    const float* f_w3    = (const float*)d_in[12];
    const float* f_b3    = (const float*)d_in[13];
    const float* ch_raw  = (const float*)d_in[14];
    const float* gate    = (const float*)d_in[15];
    float* out = (float*)d_out;

    k_setup<<<1, 32>>>(cell, ch_raw);
    k_zero<<<2048, 256>>>();
    k_radial<<<3073, 64>>>(f_w1, f_b1, f_w2, f_b2, f_w3, f_b3);
    k_lnproj<<<1024, 256>>>(h, ln_w, ln_b, in_w, in_b);
    k_scatter<<<1024, 256>>>(pos);
    k_fft_zy<<<512, 64>>>();
    k_fft_x_filter<<<512, 64>>>();
    k_ifft_yz<<<512, 64>>>();
    k_gather<<<1024, 256>>>(h, pos, out_w, gate, out);
}